// round 1
// baseline (speedup 1.0000x reference)
#include <cuda_runtime.h>
#include <math.h>

#define NN 100000
#define NE 1600000
#define KIN 256
#define HD 128

// ---------------- device scratch (no allocation allowed) ----------------
__device__ float g_el[(size_t)NN * HD];   // 51.2 MB
__device__ float g_er[(size_t)NN * HD];   // 51.2 MB
__device__ float g_s[(size_t)NE * 4];     // 25.6 MB edge scores
__device__ float g_max[NN * 4];
__device__ float g_den[NN * 4];
__device__ int   g_deg[NN];
__device__ int   g_off[NN + 1];
__device__ int   g_cur[NN];
__device__ int   g_eid[NE];
__device__ int   g_bsum[128];

__device__ __forceinline__ float lrelu(float x) { return x > 0.f ? x : 0.2f * x; }

// ---------------- GEMM: C[M x 128] = A[M x 256] * W[256 x 128] + bias ----
// BM=128, BN=128, BK=16, 256 threads, 8x8 per thread.
__global__ void __launch_bounds__(256) gemm_kernel(const float* __restrict__ A,
                                                   const float* __restrict__ W,
                                                   const float* __restrict__ bias,
                                                   int which) {
    float* C = which ? g_er : g_el;
    __shared__ float As[16][132];   // transposed A tile, padded
    __shared__ float Bs[16][128];

    const int tid = threadIdx.x;
    const int m0  = blockIdx.x * 128;
    const int ty  = tid >> 4;       // 0..15
    const int tx  = tid & 15;       // 0..15

    float acc[8][8];
#pragma unroll
    for (int i = 0; i < 8; i++)
#pragma unroll
        for (int j = 0; j < 8; j++) acc[i][j] = 0.f;

    for (int k0 = 0; k0 < KIN; k0 += 16) {
        // Load A tile: 128 rows x 16 cols = 512 float4 slots, 2 per thread
#pragma unroll
        for (int i = 0; i < 2; i++) {
            int s = tid * 2 + i;
            int r = s >> 2;
            int c = (s & 3) * 4;
            int gr = m0 + r;
            float4 v = make_float4(0.f, 0.f, 0.f, 0.f);
            if (gr < NN) v = *(const float4*)(A + (size_t)gr * KIN + k0 + c);
            As[c + 0][r] = v.x;
            As[c + 1][r] = v.y;
            As[c + 2][r] = v.z;
            As[c + 3][r] = v.w;
        }
        // Load B tile: 16 rows x 128 cols
#pragma unroll
        for (int i = 0; i < 2; i++) {
            int s = tid * 2 + i;
            int r = s >> 5;
            int c = (s & 31) * 4;
            *(float4*)&Bs[r][c] = *(const float4*)(W + (size_t)(k0 + r) * HD + c);
        }
        __syncthreads();

#pragma unroll
        for (int kk = 0; kk < 16; kk++) {
            float a[8], b[8];
            *(float4*)&a[0] = *(float4*)&As[kk][ty * 8];
            *(float4*)&a[4] = *(float4*)&As[kk][ty * 8 + 4];
            *(float4*)&b[0] = *(float4*)&Bs[kk][tx * 8];
            *(float4*)&b[4] = *(float4*)&Bs[kk][tx * 8 + 4];
#pragma unroll
            for (int i = 0; i < 8; i++)
#pragma unroll
                for (int j = 0; j < 8; j++) acc[i][j] = fmaf(a[i], b[j], acc[i][j]);
        }
        __syncthreads();
    }

#pragma unroll
    for (int i = 0; i < 8; i++) {
        int gr = m0 + ty * 8 + i;
        if (gr < NN) {
#pragma unroll
            for (int j = 0; j < 8; j += 4) {
                int col = tx * 8 + j;
                float4 v;
                v.x = acc[i][j + 0] + bias[col + 0];
                v.y = acc[i][j + 1] + bias[col + 1];
                v.z = acc[i][j + 2] + bias[col + 2];
                v.w = acc[i][j + 3] + bias[col + 3];
                *(float4*)(C + (size_t)gr * HD + col) = v;
            }
        }
    }
}

// ---------------- CSR build ----------------
__global__ void zero_deg_kernel() {
    int i = blockIdx.x * blockDim.x + threadIdx.x;
    if (i < NN) g_deg[i] = 0;
}

__global__ void count_kernel(const int* __restrict__ dst) {
    int e = blockIdx.x * blockDim.x + threadIdx.x;
    if (e < NE) atomicAdd(&g_deg[dst[e]], 1);
}

__global__ void scan1_kernel() {   // 98 blocks x 1024
    __shared__ int sm[1024];
    int i = blockIdx.x * 1024 + threadIdx.x;
    int v = (i < NN) ? g_deg[i] : 0;
    sm[threadIdx.x] = v;
    __syncthreads();
    for (int off = 1; off < 1024; off <<= 1) {
        int t = (threadIdx.x >= off) ? sm[threadIdx.x - off] : 0;
        __syncthreads();
        sm[threadIdx.x] += t;
        __syncthreads();
    }
    if (i < NN) g_off[i] = sm[threadIdx.x] - v;   // exclusive
    if (threadIdx.x == 1023) g_bsum[blockIdx.x] = sm[1023];
}

__global__ void scan2_kernel() {   // 1 block x 128, scans 98 block sums
    __shared__ int sm[128];
    int v = (threadIdx.x < 98) ? g_bsum[threadIdx.x] : 0;
    sm[threadIdx.x] = v;
    __syncthreads();
    for (int off = 1; off < 128; off <<= 1) {
        int t = (threadIdx.x >= off) ? sm[threadIdx.x - off] : 0;
        __syncthreads();
        sm[threadIdx.x] += t;
        __syncthreads();
    }
    if (threadIdx.x < 98) g_bsum[threadIdx.x] = sm[threadIdx.x] - v;  // exclusive
}

__global__ void scan3_kernel() {   // 98 blocks x 1024
    int i = blockIdx.x * 1024 + threadIdx.x;
    if (i < NN) {
        int o = g_off[i] + g_bsum[i >> 10];
        g_off[i] = o;
        g_cur[i] = o;
    }
    if (i == 0) g_off[NN] = NE;
}

__global__ void fill_kernel(const int* __restrict__ dst) {
    int e = blockIdx.x * blockDim.x + threadIdx.x;
    if (e < NE) {
        int p = atomicAdd(&g_cur[dst[e]], 1);
        g_eid[p] = e;
    }
}

// ---------------- main pull-based flash-softmax aggregation --------------
// One warp per destination node. Lane l: head h = l>>3, covers d = (l&7)*4 .. +3
// i.e. feature offset 4*l within the 128-wide node feature vector.
__global__ void __launch_bounds__(256) node_kernel(const int* __restrict__ src,
                                                   const float* __restrict__ attn,
                                                   float* __restrict__ out) {
    int warp = (blockIdx.x * blockDim.x + threadIdx.x) >> 5;
    int lane = threadIdx.x & 31;
    if (warp >= NN) return;
    const int v = warp;

    const float4 rv = *(const float4*)&g_er[(size_t)v * HD + lane * 4];
    const float4 av = *(const float4*)&attn[lane * 4];

    int beg = g_off[v];
    int end = g_off[v + 1];

    float mval = -INFINITY;
    float lsum = 0.f;
    float4 acc = make_float4(0.f, 0.f, 0.f, 0.f);

    int e = 0, u = 0;
    if (beg < end) {
        e = g_eid[beg];
        u = src[e];
    }
    for (int ei = beg; ei < end; ei++) {
        const int ee = e;
        const int ue = u;
        if (ei + 1 < end) {          // prefetch next index chain
            e = g_eid[ei + 1];
            u = src[e];
        }
        const float4 lu = *(const float4*)&g_el[(size_t)ue * HD + lane * 4];

        float p = lrelu(lu.x + rv.x) * av.x;
        p = fmaf(lrelu(lu.y + rv.y), av.y, p);
        p = fmaf(lrelu(lu.z + rv.z), av.z, p);
        p = fmaf(lrelu(lu.w + rv.w), av.w, p);
        // reduce within 8-lane head group
        p += __shfl_xor_sync(0xffffffffu, p, 1);
        p += __shfl_xor_sync(0xffffffffu, p, 2);
        p += __shfl_xor_sync(0xffffffffu, p, 4);

        if ((lane & 7) == 0) g_s[(size_t)ee * 4 + (lane >> 3)] = p;

        float mnew  = fmaxf(mval, p);
        float scale = __expf(mval - mnew);
        float w     = __expf(p - mnew);
        lsum = lsum * scale + w;
        acc.x = fmaf(acc.x, scale, w * lu.x);
        acc.y = fmaf(acc.y, scale, w * lu.y);
        acc.z = fmaf(acc.z, scale, w * lu.z);
        acc.w = fmaf(acc.w, scale, w * lu.w);
        mval = mnew;
    }

    float inv = (lsum > 0.f) ? (1.0f / lsum) : 0.f;
    float4 r;
    r.x = acc.x * inv;
    r.y = acc.y * inv;
    r.z = acc.z * inv;
    r.w = acc.w * inv;
    // sum across the 4 heads (lanes l, l^8, l^16, l^24 hold the same d-slice)
    r.x += __shfl_xor_sync(0xffffffffu, r.x, 8);
    r.y += __shfl_xor_sync(0xffffffffu, r.y, 8);
    r.z += __shfl_xor_sync(0xffffffffu, r.z, 8);
    r.w += __shfl_xor_sync(0xffffffffu, r.w, 8);
    r.x += __shfl_xor_sync(0xffffffffu, r.x, 16);
    r.y += __shfl_xor_sync(0xffffffffu, r.y, 16);
    r.z += __shfl_xor_sync(0xffffffffu, r.z, 16);
    r.w += __shfl_xor_sync(0xffffffffu, r.w, 16);

    if (lane < 8) {
        float4 o;
        o.x = r.x * 0.25f; o.y = r.y * 0.25f; o.z = r.z * 0.25f; o.w = r.w * 0.25f;
        *(float4*)&out[(size_t)v * 32 + lane * 4] = o;
    }
    if ((lane & 7) == 0) {
        int h = lane >> 3;
        g_max[v * 4 + h] = mval;
        g_den[v * 4 + h] = lsum;
    }
}

// ---------------- per-edge attention mean ----------------
__global__ void edge_kernel(const int* __restrict__ dst, float* __restrict__ out) {
    int ee = blockIdx.x * blockDim.x + threadIdx.x;
    if (ee >= NE) return;
    float4 s = *(const float4*)&g_s[(size_t)ee * 4];
    int v = dst[ee];
    const float4 mx = *(const float4*)&g_max[v * 4];
    const float4 dn = *(const float4*)&g_den[v * 4];
    float am = __expf(s.x - mx.x) / dn.x;
    am += __expf(s.y - mx.y) / dn.y;
    am += __expf(s.z - mx.z) / dn.z;
    am += __expf(s.w - mx.w) / dn.w;
    out[(size_t)NN * 32 + ee] = 0.25f * am;
}

// ---------------- launch ----------------
extern "C" void kernel_launch(void* const* d_in, const int* in_sizes, int n_in,
                              void* d_out, int out_size) {
    const float* x     = (const float*)d_in[0];
    const float* w_src = (const float*)d_in[1];
    const float* b_src = (const float*)d_in[2];
    const float* w_dst = (const float*)d_in[3];
    const float* b_dst = (const float*)d_in[4];
    const float* attn  = (const float*)d_in[5];
    const int*   src   = (const int*)d_in[6];
    const int*   dst   = (const int*)d_in[7];
    float* out = (float*)d_out;

    const int gemm_blocks = (NN + 127) / 128;     // 782

    gemm_kernel<<<gemm_blocks, 256>>>(x, w_src, b_src, 0);
    gemm_kernel<<<gemm_blocks, 256>>>(x, w_dst, b_dst, 1);

    zero_deg_kernel<<<(NN + 255) / 256, 256>>>();
    count_kernel<<<(NE + 255) / 256, 256>>>(dst);
    scan1_kernel<<<98, 1024>>>();
    scan2_kernel<<<1, 128>>>();
    scan3_kernel<<<98, 1024>>>();
    fill_kernel<<<(NE + 255) / 256, 256>>>(dst);

    node_kernel<<<(NN * 32 + 255) / 256, 256>>>(src, attn, out);
    edge_kernel<<<(NE + 255) / 256, 256>>>(dst, out);
}

// round 3
// speedup vs baseline: 1.6207x; 1.6207x over previous
#include <cuda_runtime.h>
#include <cuda_bf16.h>
#include <math.h>
#include <stdint.h>

#define NN 100000
#define NE 1600000
#define KIN 256
#define HD 128

// ---------------- device scratch (no allocation allowed) ----------------
__device__ float g_el[(size_t)NN * HD];   // 51.2 MB
__device__ float g_er[(size_t)NN * HD];   // 51.2 MB
__device__ float g_s[(size_t)NE * 4];     // 25.6 MB edge scores
__device__ float g_max[NN * 4];
__device__ float g_den[NN * 4];
__device__ int   g_deg[NN];
__device__ int   g_off[NN + 1];
__device__ int   g_cur[NN];
__device__ int   g_eid[NE];
__device__ int   g_bsum[128];

// bf16-split transposed weights: [gemm][chunk][n][hi32|lo32]
__device__ __nv_bfloat16 g_bw[2 * 8 * 128 * 64];   // 256 KB

__device__ __forceinline__ float lrelu(float x) { return x > 0.f ? x : 0.2f * x; }

__device__ __forceinline__ uint32_t smem_u32(const void* p) {
    uint32_t a;
    asm("{ .reg .u64 t; cvta.to.shared.u64 t, %1; cvt.u32.u64 %0, t; }"
        : "=r"(a) : "l"(p));
    return a;
}
__device__ __forceinline__ uint32_t SW(uint32_t x) { return x ^ ((x >> 3) & 0x70); }

__device__ __forceinline__ void bsplit(float v, unsigned short& h, unsigned short& l) {
    __nv_bfloat16 hb = __float2bfloat16_rn(v);
    float r = v - __bfloat162float(hb);
    __nv_bfloat16 lb = __float2bfloat16_rn(r);
    h = __bfloat16_as_ushort(hb);
    l = __bfloat16_as_ushort(lb);
}

__device__ __forceinline__ void ldm_x4(uint32_t& r0, uint32_t& r1, uint32_t& r2,
                                       uint32_t& r3, uint32_t a) {
    asm volatile("ldmatrix.sync.aligned.m8n8.x4.shared.b16 {%0,%1,%2,%3}, [%4];"
                 : "=r"(r0), "=r"(r1), "=r"(r2), "=r"(r3) : "r"(a));
}
__device__ __forceinline__ void ldm_x2(uint32_t& r0, uint32_t& r1, uint32_t a) {
    asm volatile("ldmatrix.sync.aligned.m8n8.x2.shared.b16 {%0,%1}, [%2];"
                 : "=r"(r0), "=r"(r1) : "r"(a));
}
__device__ __forceinline__ void mma_bf16(float* d, const uint32_t* a,
                                         uint32_t b0, uint32_t b1) {
    asm volatile(
        "mma.sync.aligned.m16n8k16.row.col.f32.bf16.bf16.f32 "
        "{%0,%1,%2,%3}, {%4,%5,%6,%7}, {%8,%9}, {%0,%1,%2,%3};"
        : "+f"(d[0]), "+f"(d[1]), "+f"(d[2]), "+f"(d[3])
        : "r"(a[0]), "r"(a[1]), "r"(a[2]), "r"(a[3]), "r"(b0), "r"(b1));
}
__device__ __forceinline__ void cp16(uint32_t dst, const void* src) {
    asm volatile("cp.async.cg.shared.global [%0], [%1], 16;"
                 :: "r"(dst), "l"(src) : "memory");
}
__device__ __forceinline__ void cp_commit() {
    asm volatile("cp.async.commit_group;" ::: "memory");
}
__device__ __forceinline__ void cp_wait0() {
    asm volatile("cp.async.wait_group 0;" ::: "memory");
}

// ---------------- weight transpose + bf16 split ----------------
__global__ void wsplit_kernel(const float* __restrict__ w_src,
                              const float* __restrict__ w_dst) {
    int i = blockIdx.x * blockDim.x + threadIdx.x;
    if (i >= 2 * 8 * 128 * 32) return;
    int g  = i >> 15;
    int c  = (i >> 12) & 7;
    int n  = (i >> 5) & 127;
    int kk = i & 31;
    const float* W = g ? w_dst : w_src;
    float v = W[(size_t)(c * 32 + kk) * HD + n];
    unsigned short h, l;
    bsplit(v, h, l);
    __nv_bfloat16* row = g_bw + ((size_t)(g * 8 + c) * 128 + n) * 64;
    row[kk]      = __ushort_as_bfloat16(h);
    row[32 + kk] = __ushort_as_bfloat16(l);
}

// ------------- fused dual GEMM via mma.sync bf16 (3-term split) ----------
// CTA: 128 rows x 256 combined cols (el: 0-127, er: 128-255). 512 threads.
// Warp w: m-off 64*(w&1), combined n-off 32*(w>>1). Warp tile 64x32.
// SMEM stage (49152B): A[128 rows][hi32|lo32 bf16 =128B] then B[256 n][128B].
#define STAGE_BYTES 49152
#define SM_TOT (2 * STAGE_BYTES + 1024)

__global__ void __launch_bounds__(512) gemm2_kernel(const float* __restrict__ x,
                                                    const float* __restrict__ b_src,
                                                    const float* __restrict__ b_dst) {
    extern __shared__ char smem_raw[];
    char* smem = (char*)(((uintptr_t)smem_raw + 1023) & ~(uintptr_t)1023);
    const uint32_t sb = smem_u32(smem);

    const int tid  = threadIdx.x;
    const int w    = tid >> 5;
    const int lane = tid & 31;
    const int m0   = blockIdx.x * 128;

    const int wm   = (w & 1) * 64;
    const int wnc  = (w >> 1) * 32;
    const int gm   = wnc >> 7;          // 0 = el, 1 = er
    const int wn   = wnc & 127;

    float acc[4][4][4];
#pragma unroll
    for (int a = 0; a < 4; a++)
#pragma unroll
        for (int b = 0; b < 4; b++)
#pragma unroll
            for (int d = 0; d < 4; d++) acc[a][b][d] = 0.f;

    // per-lane ldmatrix base offsets
    const uint32_t a_base = (uint32_t)((wm + ((lane >> 3) & 1) * 8 + (lane & 7)) * 128 +
                                       ((lane >> 4) & 1) * 16);
    const uint32_t b_base = (uint32_t)(gm * 16384 + (wn + (lane & 7)) * 128 +
                                       ((lane & 8) ? 16 : 0));

    // A prefetch assignment: thread -> row (tid>>2), 8 floats at (tid&3)*8
    const int ar  = tid >> 2;
    const int aks = (tid & 3) * 8;
    const int gr  = m0 + ar;
    const bool aok = gr < NN;
    const uint32_t a_sts = (uint32_t)(ar * 128 + (tid & 3) * 16);

    float4 f0, f1;

    auto loadA = [&](int c) {
        if (aok) {
            const float4* p = (const float4*)(x + (size_t)gr * KIN + c * 32 + aks);
            f0 = p[0];
            f1 = p[1];
        } else {
            f0 = make_float4(0.f, 0.f, 0.f, 0.f);
            f1 = f0;
        }
    };
    auto stsA = [&](int buf) {
        float v[8] = {f0.x, f0.y, f0.z, f0.w, f1.x, f1.y, f1.z, f1.w};
        unsigned short h[8], l[8];
#pragma unroll
        for (int i = 0; i < 8; i++) bsplit(v[i], h[i], l[i]);
        uint4 uh, ul;
        uh.x = (uint32_t)h[0] | ((uint32_t)h[1] << 16);
        uh.y = (uint32_t)h[2] | ((uint32_t)h[3] << 16);
        uh.z = (uint32_t)h[4] | ((uint32_t)h[5] << 16);
        uh.w = (uint32_t)h[6] | ((uint32_t)h[7] << 16);
        ul.x = (uint32_t)l[0] | ((uint32_t)l[1] << 16);
        ul.y = (uint32_t)l[2] | ((uint32_t)l[3] << 16);
        ul.z = (uint32_t)l[4] | ((uint32_t)l[5] << 16);
        ul.w = (uint32_t)l[6] | ((uint32_t)l[7] << 16);
        char* base = smem + buf * STAGE_BYTES;
        *(uint4*)(base + SW(a_sts))      = uh;
        *(uint4*)(base + SW(a_sts + 64)) = ul;
    };
    auto cpB = [&](int c, int buf) {
        const uint32_t dstb = sb + buf * STAGE_BYTES + 16384;
#pragma unroll
        for (int p = 0; p < 4; p++) {
            int q   = tid + 512 * p;
            int g   = q >> 10;
            int rem = q & 1023;
            uint32_t off = (uint32_t)(g * 16384 + (rem >> 3) * 128 + (rem & 7) * 16);
            const char* src = (const char*)g_bw + (size_t)(g * 8 + c) * 16384 +
                              (rem >> 3) * 128 + (rem & 7) * 16;
            cp16(dstb + SW(off), src);
        }
    };

    // prologue: chunk 0
    loadA(0);
    cpB(0, 0);
    cp_commit();
    stsA(0);
    cp_wait0();
    __syncthreads();

    for (int c = 0; c < 8; c++) {
        const uint32_t stg = sb + (uint32_t)(c & 1) * STAGE_BYTES;
        if (c < 7) {
            loadA(c + 1);
            cpB(c + 1, (c + 1) & 1);
            cp_commit();
        }
#pragma unroll
        for (int kh = 0; kh < 2; kh++) {
            uint32_t aH[4][4], aL[4][4];
#pragma unroll
            for (int mt = 0; mt < 4; mt++) {
                uint32_t off = a_base + mt * 2048 + kh * 32;
                ldm_x4(aH[mt][0], aH[mt][1], aH[mt][2], aH[mt][3], stg + SW(off));
                ldm_x4(aL[mt][0], aL[mt][1], aL[mt][2], aL[mt][3], stg + SW(off + 64));
            }
#pragma unroll
            for (int nt = 0; nt < 4; nt++) {
                uint32_t offB = b_base + nt * 1024 + kh * 32;
                uint32_t bh0, bh1, bl0, bl1;
                ldm_x2(bh0, bh1, stg + 16384 + SW(offB));
                ldm_x2(bl0, bl1, stg + 16384 + SW(offB + 64));
#pragma unroll
                for (int mt = 0; mt < 4; mt++) {
                    mma_bf16(acc[mt][nt], aH[mt], bh0, bh1);
                    mma_bf16(acc[mt][nt], aH[mt], bl0, bl1);
                    mma_bf16(acc[mt][nt], aL[mt], bh0, bh1);
                }
            }
        }
        if (c < 7) {
            stsA((c + 1) & 1);
            cp_wait0();
        }
        __syncthreads();
    }

    // epilogue
    float* C = gm ? g_er : g_el;
    const float* bias = gm ? b_dst : b_src;
#pragma unroll
    for (int nt = 0; nt < 4; nt++) {
        int n = wn + nt * 8 + (lane & 3) * 2;
        float b0v = bias[n];
        float b1v = bias[n + 1];
#pragma unroll
        for (int mt = 0; mt < 4; mt++) {
            int m = m0 + wm + mt * 16 + (lane >> 2);
            if (m < NN) {
                float2 o = make_float2(acc[mt][nt][0] + b0v, acc[mt][nt][1] + b1v);
                *(float2*)(C + (size_t)m * HD + n) = o;
            }
            if (m + 8 < NN) {
                float2 o = make_float2(acc[mt][nt][2] + b0v, acc[mt][nt][3] + b1v);
                *(float2*)(C + (size_t)(m + 8) * HD + n) = o;
            }
        }
    }
}

// ---------------- CSR build ----------------
__global__ void zero_deg_kernel() {
    int i = blockIdx.x * blockDim.x + threadIdx.x;
    if (i < NN) g_deg[i] = 0;
}

__global__ void count_kernel(const int* __restrict__ dst) {
    int e = blockIdx.x * blockDim.x + threadIdx.x;
    if (e < NE) atomicAdd(&g_deg[dst[e]], 1);
}

__global__ void scan1_kernel() {   // 98 blocks x 1024
    __shared__ int sm[1024];
    int i = blockIdx.x * 1024 + threadIdx.x;
    int v = (i < NN) ? g_deg[i] : 0;
    sm[threadIdx.x] = v;
    __syncthreads();
    for (int off = 1; off < 1024; off <<= 1) {
        int t = (threadIdx.x >= off) ? sm[threadIdx.x - off] : 0;
        __syncthreads();
        sm[threadIdx.x] += t;
        __syncthreads();
    }
    if (i < NN) g_off[i] = sm[threadIdx.x] - v;   // exclusive
    if (threadIdx.x == 1023) g_bsum[blockIdx.x] = sm[1023];
}

__global__ void scan2_kernel() {   // 1 block x 128
    __shared__ int sm[128];
    int v = (threadIdx.x < 98) ? g_bsum[threadIdx.x] : 0;
    sm[threadIdx.x] = v;
    __syncthreads();
    for (int off = 1; off < 128; off <<= 1) {
        int t = (threadIdx.x >= off) ? sm[threadIdx.x - off] : 0;
        __syncthreads();
        sm[threadIdx.x] += t;
        __syncthreads();
    }
    if (threadIdx.x < 98) g_bsum[threadIdx.x] = sm[threadIdx.x] - v;
}

__global__ void scan3_kernel() {   // 98 blocks x 1024
    int i = blockIdx.x * 1024 + threadIdx.x;
    if (i < NN) {
        int o = g_off[i] + g_bsum[i >> 10];
        g_off[i] = o;
        g_cur[i] = o;
    }
    if (i == 0) g_off[NN] = NE;
}

__global__ void fill_kernel(const int* __restrict__ dst) {
    int e = blockIdx.x * blockDim.x + threadIdx.x;
    if (e < NE) {
        int p = atomicAdd(&g_cur[dst[e]], 1);
        g_eid[p] = e;
    }
}

// ---------------- pull-based flash-softmax aggregation --------------
__global__ void __launch_bounds__(256) node_kernel(const int* __restrict__ src,
                                                   const float* __restrict__ attn,
                                                   float* __restrict__ out) {
    int warp = (blockIdx.x * blockDim.x + threadIdx.x) >> 5;
    int lane = threadIdx.x & 31;
    if (warp >= NN) return;
    const int v = warp;

    const float4 rv = *(const float4*)&g_er[(size_t)v * HD + lane * 4];
    const float4 av = *(const float4*)&attn[lane * 4];

    int beg = g_off[v];
    int end = g_off[v + 1];

    float mval = -INFINITY;
    float lsum = 0.f;
    float4 acc = make_float4(0.f, 0.f, 0.f, 0.f);

    int e = 0, u = 0;
    if (beg < end) {
        e = g_eid[beg];
        u = src[e];
    }
    for (int ei = beg; ei < end; ei++) {
        const int ee = e;
        const int ue = u;
        if (ei + 1 < end) {
            e = g_eid[ei + 1];
            u = src[e];
        }
        const float4 lu = *(const float4*)&g_el[(size_t)ue * HD + lane * 4];

        float p = lrelu(lu.x + rv.x) * av.x;
        p = fmaf(lrelu(lu.y + rv.y), av.y, p);
        p = fmaf(lrelu(lu.z + rv.z), av.z, p);
        p = fmaf(lrelu(lu.w + rv.w), av.w, p);
        p += __shfl_xor_sync(0xffffffffu, p, 1);
        p += __shfl_xor_sync(0xffffffffu, p, 2);
        p += __shfl_xor_sync(0xffffffffu, p, 4);

        if ((lane & 7) == 0) g_s[(size_t)ee * 4 + (lane >> 3)] = p;

        float mnew  = fmaxf(mval, p);
        float scale = __expf(mval - mnew);
        float ww    = __expf(p - mnew);
        lsum = lsum * scale + ww;
        acc.x = fmaf(acc.x, scale, ww * lu.x);
        acc.y = fmaf(acc.y, scale, ww * lu.y);
        acc.z = fmaf(acc.z, scale, ww * lu.z);
        acc.w = fmaf(acc.w, scale, ww * lu.w);
        mval = mnew;
    }

    float inv = (lsum > 0.f) ? (1.0f / lsum) : 0.f;
    float4 r;
    r.x = acc.x * inv;
    r.y = acc.y * inv;
    r.z = acc.z * inv;
    r.w = acc.w * inv;
    r.x += __shfl_xor_sync(0xffffffffu, r.x, 8);
    r.y += __shfl_xor_sync(0xffffffffu, r.y, 8);
    r.z += __shfl_xor_sync(0xffffffffu, r.z, 8);
    r.w += __shfl_xor_sync(0xffffffffu, r.w, 8);
    r.x += __shfl_xor_sync(0xffffffffu, r.x, 16);
    r.y += __shfl_xor_sync(0xffffffffu, r.y, 16);
    r.z += __shfl_xor_sync(0xffffffffu, r.z, 16);
    r.w += __shfl_xor_sync(0xffffffffu, r.w, 16);

    if (lane < 8) {
        float4 o;
        o.x = r.x * 0.25f; o.y = r.y * 0.25f; o.z = r.z * 0.25f; o.w = r.w * 0.25f;
        *(float4*)&out[(size_t)v * 32 + lane * 4] = o;
    }
    if ((lane & 7) == 0) {
        int h = lane >> 3;
        g_max[v * 4 + h] = mval;
        g_den[v * 4 + h] = lsum;
    }
}

// ---------------- per-edge attention mean ----------------
__global__ void edge_kernel(const int* __restrict__ dst, float* __restrict__ out) {
    int ee = blockIdx.x * blockDim.x + threadIdx.x;
    if (ee >= NE) return;
    float4 s = *(const float4*)&g_s[(size_t)ee * 4];
    int v = dst[ee];
    const float4 mx = *(const float4*)&g_max[v * 4];
    const float4 dn = *(const float4*)&g_den[v * 4];
    float am = __expf(s.x - mx.x) / dn.x;
    am += __expf(s.y - mx.y) / dn.y;
    am += __expf(s.z - mx.z) / dn.z;
    am += __expf(s.w - mx.w) / dn.w;
    out[(size_t)NN * 32 + ee] = 0.25f * am;
}

// ---------------- launch ----------------
extern "C" void kernel_launch(void* const* d_in, const int* in_sizes, int n_in,
                              void* d_out, int out_size) {
    const float* x     = (const float*)d_in[0];
    const float* w_src = (const float*)d_in[1];
    const float* b_src = (const float*)d_in[2];
    const float* w_dst = (const float*)d_in[3];
    const float* b_dst = (const float*)d_in[4];
    const float* attn  = (const float*)d_in[5];
    const int*   src   = (const int*)d_in[6];
    const int*   dst   = (const int*)d_in[7];
    float* out = (float*)d_out;

    cudaFuncSetAttribute(gemm2_kernel, cudaFuncAttributeMaxDynamicSharedMemorySize, SM_TOT);

    wsplit_kernel<<<(2 * 8 * 128 * 32 + 255) / 256, 256>>>(w_src, w_dst);

    const int gemm_blocks = (NN + 127) / 128;     // 782
    gemm2_kernel<<<gemm_blocks, 512, SM_TOT>>>(x, b_src, b_dst);

    zero_deg_kernel<<<(NN + 255) / 256, 256>>>();
    count_kernel<<<(NE + 255) / 256, 256>>>(dst);
    scan1_kernel<<<98, 1024>>>();
    scan2_kernel<<<1, 128>>>();
    scan3_kernel<<<98, 1024>>>();
    fill_kernel<<<(NE + 255) / 256, 256>>>(dst);

    node_kernel<<<(NN * 32 + 255) / 256, 256>>>(src, attn, out);
    edge_kernel<<<(NE + 255) / 256, 256>>>(dst, out);
}

// round 4
// speedup vs baseline: 1.7820x; 1.0995x over previous
#include <cuda_runtime.h>
#include <cuda_bf16.h>
#include <math.h>
#include <stdint.h>

#define NN 100000
#define NE 1600000
#define KIN 256
#define HD 128

// ---------------- device scratch (no allocation allowed) ----------------
__device__ float g_el[(size_t)NN * HD];   // 51.2 MB
__device__ float g_er[(size_t)NN * HD];   // 51.2 MB
__device__ float g_s[(size_t)NE * 4];     // 25.6 MB edge scores (CSR order)
__device__ int   g_deg[NN];
__device__ int   g_off[NN + 1];
__device__ int   g_cur[NN];
__device__ int2  g_e[NE];                 // {edge_id, src_node} in CSR order
__device__ int   g_bsum[128];

// bf16-split transposed weights: [gemm][chunk][n][hi32|lo32]
__device__ __nv_bfloat16 g_bw[2 * 8 * 128 * 64];   // 256 KB

__device__ __forceinline__ float lrelu(float x) { return x > 0.f ? x : 0.2f * x; }

__device__ __forceinline__ uint32_t smem_u32(const void* p) {
    uint32_t a;
    asm("{ .reg .u64 t; cvta.to.shared.u64 t, %1; cvt.u32.u64 %0, t; }"
        : "=r"(a) : "l"(p));
    return a;
}
__device__ __forceinline__ uint32_t SW(uint32_t x) { return x ^ ((x >> 3) & 0x70); }

__device__ __forceinline__ void bsplit(float v, unsigned short& h, unsigned short& l) {
    __nv_bfloat16 hb = __float2bfloat16_rn(v);
    float r = v - __bfloat162float(hb);
    __nv_bfloat16 lb = __float2bfloat16_rn(r);
    h = __bfloat16_as_ushort(hb);
    l = __bfloat16_as_ushort(lb);
}

__device__ __forceinline__ void ldm_x4(uint32_t& r0, uint32_t& r1, uint32_t& r2,
                                       uint32_t& r3, uint32_t a) {
    asm volatile("ldmatrix.sync.aligned.m8n8.x4.shared.b16 {%0,%1,%2,%3}, [%4];"
                 : "=r"(r0), "=r"(r1), "=r"(r2), "=r"(r3) : "r"(a));
}
__device__ __forceinline__ void ldm_x2(uint32_t& r0, uint32_t& r1, uint32_t a) {
    asm volatile("ldmatrix.sync.aligned.m8n8.x2.shared.b16 {%0,%1}, [%2];"
                 : "=r"(r0), "=r"(r1) : "r"(a));
}
__device__ __forceinline__ void mma_bf16(float* d, const uint32_t* a,
                                         uint32_t b0, uint32_t b1) {
    asm volatile(
        "mma.sync.aligned.m16n8k16.row.col.f32.bf16.bf16.f32 "
        "{%0,%1,%2,%3}, {%4,%5,%6,%7}, {%8,%9}, {%0,%1,%2,%3};"
        : "+f"(d[0]), "+f"(d[1]), "+f"(d[2]), "+f"(d[3])
        : "r"(a[0]), "r"(a[1]), "r"(a[2]), "r"(a[3]), "r"(b0), "r"(b1));
}
__device__ __forceinline__ void cp16(uint32_t dst, const void* src) {
    asm volatile("cp.async.cg.shared.global [%0], [%1], 16;"
                 :: "r"(dst), "l"(src) : "memory");
}
__device__ __forceinline__ void cp_commit() {
    asm volatile("cp.async.commit_group;" ::: "memory");
}
__device__ __forceinline__ void cp_wait0() {
    asm volatile("cp.async.wait_group 0;" ::: "memory");
}

// ---------------- weight transpose + bf16 split ----------------
__global__ void wsplit_kernel(const float* __restrict__ w_src,
                              const float* __restrict__ w_dst) {
    int i = blockIdx.x * blockDim.x + threadIdx.x;
    if (i >= 2 * 8 * 128 * 32) return;
    int g  = i >> 15;
    int c  = (i >> 12) & 7;
    int n  = (i >> 5) & 127;
    int kk = i & 31;
    const float* W = g ? w_dst : w_src;
    float v = W[(size_t)(c * 32 + kk) * HD + n];
    unsigned short h, l;
    bsplit(v, h, l);
    __nv_bfloat16* row = g_bw + ((size_t)(g * 8 + c) * 128 + n) * 64;
    row[kk]      = __ushort_as_bfloat16(h);
    row[32 + kk] = __ushort_as_bfloat16(l);
}

// ------------- fused dual GEMM via mma.sync bf16 (3-term split) ----------
#define STAGE_BYTES 49152
#define SM_TOT (2 * STAGE_BYTES + 1024)

__global__ void __launch_bounds__(512) gemm2_kernel(const float* __restrict__ x,
                                                    const float* __restrict__ b_src,
                                                    const float* __restrict__ b_dst) {
    extern __shared__ char smem_raw[];
    char* smem = (char*)(((uintptr_t)smem_raw + 1023) & ~(uintptr_t)1023);
    const uint32_t sb = smem_u32(smem);

    const int tid  = threadIdx.x;
    const int w    = tid >> 5;
    const int lane = tid & 31;
    const int m0   = blockIdx.x * 128;

    const int wm   = (w & 1) * 64;
    const int wnc  = (w >> 1) * 32;
    const int gm   = wnc >> 7;          // 0 = el, 1 = er
    const int wn   = wnc & 127;

    float acc[4][4][4];
#pragma unroll
    for (int a = 0; a < 4; a++)
#pragma unroll
        for (int b = 0; b < 4; b++)
#pragma unroll
            for (int d = 0; d < 4; d++) acc[a][b][d] = 0.f;

    const uint32_t a_base = (uint32_t)((wm + ((lane >> 3) & 1) * 8 + (lane & 7)) * 128 +
                                       ((lane >> 4) & 1) * 16);
    const uint32_t b_base = (uint32_t)(gm * 16384 + (wn + (lane & 7)) * 128 +
                                       ((lane & 8) ? 16 : 0));

    const int ar  = tid >> 2;
    const int aks = (tid & 3) * 8;
    const int gr  = m0 + ar;
    const bool aok = gr < NN;
    const uint32_t a_sts = (uint32_t)(ar * 128 + (tid & 3) * 16);

    float4 f0, f1;

    auto loadA = [&](int c) {
        if (aok) {
            const float4* p = (const float4*)(x + (size_t)gr * KIN + c * 32 + aks);
            f0 = p[0];
            f1 = p[1];
        } else {
            f0 = make_float4(0.f, 0.f, 0.f, 0.f);
            f1 = f0;
        }
    };
    auto stsA = [&](int buf) {
        float v[8] = {f0.x, f0.y, f0.z, f0.w, f1.x, f1.y, f1.z, f1.w};
        unsigned short h[8], l[8];
#pragma unroll
        for (int i = 0; i < 8; i++) bsplit(v[i], h[i], l[i]);
        uint4 uh, ul;
        uh.x = (uint32_t)h[0] | ((uint32_t)h[1] << 16);
        uh.y = (uint32_t)h[2] | ((uint32_t)h[3] << 16);
        uh.z = (uint32_t)h[4] | ((uint32_t)h[5] << 16);
        uh.w = (uint32_t)h[6] | ((uint32_t)h[7] << 16);
        ul.x = (uint32_t)l[0] | ((uint32_t)l[1] << 16);
        ul.y = (uint32_t)l[2] | ((uint32_t)l[3] << 16);
        ul.z = (uint32_t)l[4] | ((uint32_t)l[5] << 16);
        ul.w = (uint32_t)l[6] | ((uint32_t)l[7] << 16);
        char* base = smem + buf * STAGE_BYTES;
        *(uint4*)(base + SW(a_sts))      = uh;
        *(uint4*)(base + SW(a_sts + 64)) = ul;
    };
    auto cpB = [&](int c, int buf) {
        const uint32_t dstb = sb + buf * STAGE_BYTES + 16384;
#pragma unroll
        for (int p = 0; p < 4; p++) {
            int q   = tid + 512 * p;
            int g   = q >> 10;
            int rem = q & 1023;
            uint32_t off = (uint32_t)(g * 16384 + (rem >> 3) * 128 + (rem & 7) * 16);
            const char* src = (const char*)g_bw + (size_t)(g * 8 + c) * 16384 +
                              (rem >> 3) * 128 + (rem & 7) * 16;
            cp16(dstb + SW(off), src);
        }
    };

    loadA(0);
    cpB(0, 0);
    cp_commit();
    stsA(0);
    cp_wait0();
    __syncthreads();

    for (int c = 0; c < 8; c++) {
        const uint32_t stg = sb + (uint32_t)(c & 1) * STAGE_BYTES;
        if (c < 7) {
            loadA(c + 1);
            cpB(c + 1, (c + 1) & 1);
            cp_commit();
        }
#pragma unroll
        for (int kh = 0; kh < 2; kh++) {
            uint32_t aH[4][4], aL[4][4];
#pragma unroll
            for (int mt = 0; mt < 4; mt++) {
                uint32_t off = a_base + mt * 2048 + kh * 32;
                ldm_x4(aH[mt][0], aH[mt][1], aH[mt][2], aH[mt][3], stg + SW(off));
                ldm_x4(aL[mt][0], aL[mt][1], aL[mt][2], aL[mt][3], stg + SW(off + 64));
            }
#pragma unroll
            for (int nt = 0; nt < 4; nt++) {
                uint32_t offB = b_base + nt * 1024 + kh * 32;
                uint32_t bh0, bh1, bl0, bl1;
                ldm_x2(bh0, bh1, stg + 16384 + SW(offB));
                ldm_x2(bl0, bl1, stg + 16384 + SW(offB + 64));
#pragma unroll
                for (int mt = 0; mt < 4; mt++) {
                    mma_bf16(acc[mt][nt], aH[mt], bh0, bh1);
                    mma_bf16(acc[mt][nt], aH[mt], bl0, bl1);
                    mma_bf16(acc[mt][nt], aL[mt], bh0, bh1);
                }
            }
        }
        if (c < 7) {
            stsA((c + 1) & 1);
            cp_wait0();
        }
        __syncthreads();
    }

    float* C = gm ? g_er : g_el;
    const float* bias = gm ? b_dst : b_src;
#pragma unroll
    for (int nt = 0; nt < 4; nt++) {
        int n = wn + nt * 8 + (lane & 3) * 2;
        float b0v = bias[n];
        float b1v = bias[n + 1];
#pragma unroll
        for (int mt = 0; mt < 4; mt++) {
            int m = m0 + wm + mt * 16 + (lane >> 2);
            if (m < NN) {
                float2 o = make_float2(acc[mt][nt][0] + b0v, acc[mt][nt][1] + b1v);
                *(float2*)(C + (size_t)m * HD + n) = o;
            }
            if (m + 8 < NN) {
                float2 o = make_float2(acc[mt][nt][2] + b0v, acc[mt][nt][3] + b1v);
                *(float2*)(C + (size_t)(m + 8) * HD + n) = o;
            }
        }
    }
}

// ---------------- CSR build ----------------
__global__ void zero_deg_kernel() {
    int i = blockIdx.x * blockDim.x + threadIdx.x;
    if (i < NN) g_deg[i] = 0;
}

__global__ void count_kernel(const int* __restrict__ dst) {
    int e4 = (blockIdx.x * blockDim.x + threadIdx.x) * 4;
    if (e4 < NE) {
        int4 d = *(const int4*)(dst + e4);
        atomicAdd(&g_deg[d.x], 1);
        atomicAdd(&g_deg[d.y], 1);
        atomicAdd(&g_deg[d.z], 1);
        atomicAdd(&g_deg[d.w], 1);
    }
}

__global__ void scan1_kernel() {   // 98 blocks x 1024
    __shared__ int sm[1024];
    int i = blockIdx.x * 1024 + threadIdx.x;
    int v = (i < NN) ? g_deg[i] : 0;
    sm[threadIdx.x] = v;
    __syncthreads();
    for (int off = 1; off < 1024; off <<= 1) {
        int t = (threadIdx.x >= off) ? sm[threadIdx.x - off] : 0;
        __syncthreads();
        sm[threadIdx.x] += t;
        __syncthreads();
    }
    if (i < NN) g_off[i] = sm[threadIdx.x] - v;   // exclusive
    if (threadIdx.x == 1023) g_bsum[blockIdx.x] = sm[1023];
}

__global__ void scan2_kernel() {   // 1 block x 128
    __shared__ int sm[128];
    int v = (threadIdx.x < 98) ? g_bsum[threadIdx.x] : 0;
    sm[threadIdx.x] = v;
    __syncthreads();
    for (int off = 1; off < 128; off <<= 1) {
        int t = (threadIdx.x >= off) ? sm[threadIdx.x - off] : 0;
        __syncthreads();
        sm[threadIdx.x] += t;
        __syncthreads();
    }
    if (threadIdx.x < 98) g_bsum[threadIdx.x] = sm[threadIdx.x] - v;
}

__global__ void scan3_kernel() {   // 98 blocks x 1024
    int i = blockIdx.x * 1024 + threadIdx.x;
    if (i < NN) {
        int o = g_off[i] + g_bsum[i >> 10];
        g_off[i] = o;
        g_cur[i] = o;
    }
    if (i == 0) g_off[NN] = NE;
}

__global__ void fill_kernel(const int* __restrict__ src, const int* __restrict__ dst) {
    int e4 = (blockIdx.x * blockDim.x + threadIdx.x) * 4;
    if (e4 < NE) {
        int4 d = *(const int4*)(dst + e4);
        int4 s = *(const int4*)(src + e4);
        int p;
        p = atomicAdd(&g_cur[d.x], 1); g_e[p] = make_int2(e4 + 0, s.x);
        p = atomicAdd(&g_cur[d.y], 1); g_e[p] = make_int2(e4 + 1, s.y);
        p = atomicAdd(&g_cur[d.z], 1); g_e[p] = make_int2(e4 + 2, s.z);
        p = atomicAdd(&g_cur[d.w], 1); g_e[p] = make_int2(e4 + 3, s.w);
    }
}

// ------- pull-based flash-softmax aggregation + fused edge output --------
// One warp per destination node. Lane l: head h = l>>3, d-slice (l&7)*4..+3.
__global__ void __launch_bounds__(256) node_kernel(const float* __restrict__ attn,
                                                   float* __restrict__ out) {
    int warp = (blockIdx.x * blockDim.x + threadIdx.x) >> 5;
    int lane = threadIdx.x & 31;
    if (warp >= NN) return;
    const int v = warp;

    const float4 rv = *(const float4*)&g_er[(size_t)v * HD + lane * 4];
    const float4 av = *(const float4*)&attn[lane * 4];

    const int beg = g_off[v];
    const int end = g_off[v + 1];

    float mval = -INFINITY;
    float lsum = 0.f;
    float4 acc = make_float4(0.f, 0.f, 0.f, 0.f);

    // 2-deep index prefetch, 1-deep feature prefetch
    int2 cur = make_int2(0, 0), nxt = make_int2(0, 0);
    float4 lu = make_float4(0.f, 0.f, 0.f, 0.f);
    if (beg < end) {
        cur = g_e[beg];
        lu = *(const float4*)&g_el[(size_t)cur.y * HD + lane * 4];
        if (beg + 1 < end) nxt = g_e[beg + 1];
    }

    for (int ei = beg; ei < end; ei++) {
        float4 lu_n = make_float4(0.f, 0.f, 0.f, 0.f);
        int2 nxt2 = nxt;
        if (ei + 1 < end) {
            lu_n = *(const float4*)&g_el[(size_t)nxt.y * HD + lane * 4];
            if (ei + 2 < end) nxt2 = g_e[ei + 2];
        }

        float p = lrelu(lu.x + rv.x) * av.x;
        p = fmaf(lrelu(lu.y + rv.y), av.y, p);
        p = fmaf(lrelu(lu.z + rv.z), av.z, p);
        p = fmaf(lrelu(lu.w + rv.w), av.w, p);
        p += __shfl_xor_sync(0xffffffffu, p, 1);
        p += __shfl_xor_sync(0xffffffffu, p, 2);
        p += __shfl_xor_sync(0xffffffffu, p, 4);

        // store score by CSR position: 4 lanes write one contiguous float4
        if ((lane & 7) == 0) g_s[(size_t)ei * 4 + (lane >> 3)] = p;

        float mnew  = fmaxf(mval, p);
        float scale = __expf(mval - mnew);
        float ww    = __expf(p - mnew);
        lsum = lsum * scale + ww;
        acc.x = fmaf(acc.x, scale, ww * lu.x);
        acc.y = fmaf(acc.y, scale, ww * lu.y);
        acc.z = fmaf(acc.z, scale, ww * lu.z);
        acc.w = fmaf(acc.w, scale, ww * lu.w);
        mval = mnew;

        cur = nxt;
        nxt = nxt2;
        lu = lu_n;
    }

    // ---- feature output ----
    float inv = (lsum > 0.f) ? (1.0f / lsum) : 0.f;
    float4 r;
    r.x = acc.x * inv;
    r.y = acc.y * inv;
    r.z = acc.z * inv;
    r.w = acc.w * inv;
    r.x += __shfl_xor_sync(0xffffffffu, r.x, 8);
    r.y += __shfl_xor_sync(0xffffffffu, r.y, 8);
    r.z += __shfl_xor_sync(0xffffffffu, r.z, 8);
    r.w += __shfl_xor_sync(0xffffffffu, r.w, 8);
    r.x += __shfl_xor_sync(0xffffffffu, r.x, 16);
    r.y += __shfl_xor_sync(0xffffffffu, r.y, 16);
    r.z += __shfl_xor_sync(0xffffffffu, r.z, 16);
    r.w += __shfl_xor_sync(0xffffffffu, r.w, 16);

    if (lane < 8) {
        float4 o;
        o.x = r.x * 0.25f; o.y = r.y * 0.25f; o.z = r.z * 0.25f; o.w = r.w * 0.25f;
        *(float4*)&out[(size_t)v * 32 + lane * 4] = o;
    }

    // ---- fused per-edge attention mean (phase 2) ----
    __syncwarp();
    const float m0 = __shfl_sync(0xffffffffu, mval, 0);
    const float m1 = __shfl_sync(0xffffffffu, mval, 8);
    const float m2 = __shfl_sync(0xffffffffu, mval, 16);
    const float m3 = __shfl_sync(0xffffffffu, mval, 24);
    float l0 = __shfl_sync(0xffffffffu, lsum, 0);
    float l1 = __shfl_sync(0xffffffffu, lsum, 8);
    float l2 = __shfl_sync(0xffffffffu, lsum, 16);
    float l3 = __shfl_sync(0xffffffffu, lsum, 24);
    const float i0 = (l0 > 0.f) ? 0.25f / l0 : 0.f;
    const float i1 = (l1 > 0.f) ? 0.25f / l1 : 0.f;
    const float i2 = (l2 > 0.f) ? 0.25f / l2 : 0.f;
    const float i3 = (l3 > 0.f) ? 0.25f / l3 : 0.f;

    for (int idx = beg + lane; idx < end; idx += 32) {
        float4 s4 = *(const float4*)&g_s[(size_t)idx * 4];
        int eid = g_e[idx].x;
        float am = __expf(s4.x - m0) * i0;
        am = fmaf(__expf(s4.y - m1), i1, am);
        am = fmaf(__expf(s4.z - m2), i2, am);
        am = fmaf(__expf(s4.w - m3), i3, am);
        out[(size_t)NN * 32 + eid] = am;
    }
}

// ---------------- launch ----------------
extern "C" void kernel_launch(void* const* d_in, const int* in_sizes, int n_in,
                              void* d_out, int out_size) {
    const float* x     = (const float*)d_in[0];
    const float* w_src = (const float*)d_in[1];
    const float* b_src = (const float*)d_in[2];
    const float* w_dst = (const float*)d_in[3];
    const float* b_dst = (const float*)d_in[4];
    const float* attn  = (const float*)d_in[5];
    const int*   src   = (const int*)d_in[6];
    const int*   dst   = (const int*)d_in[7];
    float* out = (float*)d_out;

    cudaFuncSetAttribute(gemm2_kernel, cudaFuncAttributeMaxDynamicSharedMemorySize, SM_TOT);

    wsplit_kernel<<<(2 * 8 * 128 * 32 + 255) / 256, 256>>>(w_src, w_dst);

    const int gemm_blocks = (NN + 127) / 128;     // 782
    gemm2_kernel<<<gemm_blocks, 512, SM_TOT>>>(x, b_src, b_dst);

    zero_deg_kernel<<<(NN + 255) / 256, 256>>>();
    count_kernel<<<(NE / 4 + 255) / 256, 256>>>(dst);
    scan1_kernel<<<98, 1024>>>();
    scan2_kernel<<<1, 128>>>();
    scan3_kernel<<<98, 1024>>>();
    fill_kernel<<<(NE / 4 + 255) / 256, 256>>>(src, dst);

    node_kernel<<<(NN * 32 + 255) / 256, 256>>>(attn, out);
}

// round 5
// speedup vs baseline: 1.9449x; 1.0914x over previous
#include <cuda_runtime.h>
#include <cuda_bf16.h>
#include <math.h>
#include <stdint.h>

#define NN 100000
#define NE 1600000
#define KIN 256
#define HD 128

// ---------------- device scratch (no allocation allowed) ----------------
__device__ float g_el[(size_t)NN * HD];   // 51.2 MB
__device__ float g_er[(size_t)NN * HD];   // 51.2 MB
__device__ float g_s[(size_t)NE * 4];     // 25.6 MB edge scores (CSR order)
__device__ int   g_deg[NN];
__device__ int   g_off[NN + 1];
__device__ int   g_cur[NN];
__device__ int2  g_e[NE];                 // {edge_id, src_node} in CSR order
__device__ int   g_bsum[128];

// bf16-split transposed weights: [gemm][chunk][n][hi32|lo32]
__device__ __nv_bfloat16 g_bw[2 * 8 * 128 * 64];   // 256 KB

__device__ __forceinline__ float lrelu(float x) { return x > 0.f ? x : 0.2f * x; }

__device__ __forceinline__ uint32_t smem_u32(const void* p) {
    uint32_t a;
    asm("{ .reg .u64 t; cvta.to.shared.u64 t, %1; cvt.u32.u64 %0, t; }"
        : "=r"(a) : "l"(p));
    return a;
}
__device__ __forceinline__ uint32_t SW(uint32_t x) { return x ^ ((x >> 3) & 0x70); }

__device__ __forceinline__ void bsplit(float v, unsigned short& h, unsigned short& l) {
    __nv_bfloat16 hb = __float2bfloat16_rn(v);
    float r = v - __bfloat162float(hb);
    __nv_bfloat16 lb = __float2bfloat16_rn(r);
    h = __bfloat16_as_ushort(hb);
    l = __bfloat16_as_ushort(lb);
}

__device__ __forceinline__ void ldm_x4(uint32_t& r0, uint32_t& r1, uint32_t& r2,
                                       uint32_t& r3, uint32_t a) {
    asm volatile("ldmatrix.sync.aligned.m8n8.x4.shared.b16 {%0,%1,%2,%3}, [%4];"
                 : "=r"(r0), "=r"(r1), "=r"(r2), "=r"(r3) : "r"(a));
}
__device__ __forceinline__ void ldm_x2(uint32_t& r0, uint32_t& r1, uint32_t a) {
    asm volatile("ldmatrix.sync.aligned.m8n8.x2.shared.b16 {%0,%1}, [%2];"
                 : "=r"(r0), "=r"(r1) : "r"(a));
}
__device__ __forceinline__ void mma_bf16(float* d, const uint32_t* a,
                                         uint32_t b0, uint32_t b1) {
    asm volatile(
        "mma.sync.aligned.m16n8k16.row.col.f32.bf16.bf16.f32 "
        "{%0,%1,%2,%3}, {%4,%5,%6,%7}, {%8,%9}, {%0,%1,%2,%3};"
        : "+f"(d[0]), "+f"(d[1]), "+f"(d[2]), "+f"(d[3])
        : "r"(a[0]), "r"(a[1]), "r"(a[2]), "r"(a[3]), "r"(b0), "r"(b1));
}
__device__ __forceinline__ void cp16(uint32_t dst, const void* src) {
    asm volatile("cp.async.cg.shared.global [%0], [%1], 16;"
                 :: "r"(dst), "l"(src) : "memory");
}
__device__ __forceinline__ void cp_commit() {
    asm volatile("cp.async.commit_group;" ::: "memory");
}
__device__ __forceinline__ void cp_wait0() {
    asm volatile("cp.async.wait_group 0;" ::: "memory");
}

// ---------------- weight transpose + bf16 split ----------------
__global__ void wsplit_kernel(const float* __restrict__ w_src,
                              const float* __restrict__ w_dst) {
    int i = blockIdx.x * blockDim.x + threadIdx.x;
    if (i >= 2 * 8 * 128 * 32) return;
    int g  = i >> 15;
    int c  = (i >> 12) & 7;
    int n  = (i >> 5) & 127;
    int kk = i & 31;
    const float* W = g ? w_dst : w_src;
    float v = W[(size_t)(c * 32 + kk) * HD + n];
    unsigned short h, l;
    bsplit(v, h, l);
    __nv_bfloat16* row = g_bw + ((size_t)(g * 8 + c) * 128 + n) * 64;
    row[kk]      = __ushort_as_bfloat16(h);
    row[32 + kk] = __ushort_as_bfloat16(l);
}

// ------------- fused dual GEMM via mma.sync bf16 (3-term split) ----------
#define STAGE_BYTES 49152
#define SM_TOT (2 * STAGE_BYTES + 1024)

__global__ void __launch_bounds__(512) gemm2_kernel(const float* __restrict__ x,
                                                    const float* __restrict__ b_src,
                                                    const float* __restrict__ b_dst) {
    extern __shared__ char smem_raw[];
    char* smem = (char*)(((uintptr_t)smem_raw + 1023) & ~(uintptr_t)1023);
    const uint32_t sb = smem_u32(smem);

    const int tid  = threadIdx.x;
    const int w    = tid >> 5;
    const int lane = tid & 31;
    const int m0   = blockIdx.x * 128;

    const int wm   = (w & 1) * 64;
    const int wnc  = (w >> 1) * 32;
    const int gm   = wnc >> 7;          // 0 = el, 1 = er
    const int wn   = wnc & 127;

    float acc[4][4][4];
#pragma unroll
    for (int a = 0; a < 4; a++)
#pragma unroll
        for (int b = 0; b < 4; b++)
#pragma unroll
            for (int d = 0; d < 4; d++) acc[a][b][d] = 0.f;

    const uint32_t a_base = (uint32_t)((wm + ((lane >> 3) & 1) * 8 + (lane & 7)) * 128 +
                                       ((lane >> 4) & 1) * 16);
    const uint32_t b_base = (uint32_t)(gm * 16384 + (wn + (lane & 7)) * 128 +
                                       ((lane & 8) ? 16 : 0));

    const int ar  = tid >> 2;
    const int aks = (tid & 3) * 8;
    const int gr  = m0 + ar;
    const bool aok = gr < NN;
    const uint32_t a_sts = (uint32_t)(ar * 128 + (tid & 3) * 16);

    float4 f0, f1;

    auto loadA = [&](int c) {
        if (aok) {
            const float4* p = (const float4*)(x + (size_t)gr * KIN + c * 32 + aks);
            f0 = p[0];
            f1 = p[1];
        } else {
            f0 = make_float4(0.f, 0.f, 0.f, 0.f);
            f1 = f0;
        }
    };
    auto stsA = [&](int buf) {
        float v[8] = {f0.x, f0.y, f0.z, f0.w, f1.x, f1.y, f1.z, f1.w};
        unsigned short h[8], l[8];
#pragma unroll
        for (int i = 0; i < 8; i++) bsplit(v[i], h[i], l[i]);
        uint4 uh, ul;
        uh.x = (uint32_t)h[0] | ((uint32_t)h[1] << 16);
        uh.y = (uint32_t)h[2] | ((uint32_t)h[3] << 16);
        uh.z = (uint32_t)h[4] | ((uint32_t)h[5] << 16);
        uh.w = (uint32_t)h[6] | ((uint32_t)h[7] << 16);
        ul.x = (uint32_t)l[0] | ((uint32_t)l[1] << 16);
        ul.y = (uint32_t)l[2] | ((uint32_t)l[3] << 16);
        ul.z = (uint32_t)l[4] | ((uint32_t)l[5] << 16);
        ul.w = (uint32_t)l[6] | ((uint32_t)l[7] << 16);
        char* base = smem + buf * STAGE_BYTES;
        *(uint4*)(base + SW(a_sts))      = uh;
        *(uint4*)(base + SW(a_sts + 64)) = ul;
    };
    auto cpB = [&](int c, int buf) {
        const uint32_t dstb = sb + buf * STAGE_BYTES + 16384;
#pragma unroll
        for (int p = 0; p < 4; p++) {
            int q   = tid + 512 * p;
            int g   = q >> 10;
            int rem = q & 1023;
            uint32_t off = (uint32_t)(g * 16384 + (rem >> 3) * 128 + (rem & 7) * 16);
            const char* src = (const char*)g_bw + (size_t)(g * 8 + c) * 16384 +
                              (rem >> 3) * 128 + (rem & 7) * 16;
            cp16(dstb + SW(off), src);
        }
    };

    loadA(0);
    cpB(0, 0);
    cp_commit();
    stsA(0);
    cp_wait0();
    __syncthreads();

    for (int c = 0; c < 8; c++) {
        const uint32_t stg = sb + (uint32_t)(c & 1) * STAGE_BYTES;
        if (c < 7) {
            loadA(c + 1);
            cpB(c + 1, (c + 1) & 1);
            cp_commit();
        }
#pragma unroll
        for (int kh = 0; kh < 2; kh++) {
            uint32_t aH[4][4], aL[4][4];
#pragma unroll
            for (int mt = 0; mt < 4; mt++) {
                uint32_t off = a_base + mt * 2048 + kh * 32;
                ldm_x4(aH[mt][0], aH[mt][1], aH[mt][2], aH[mt][3], stg + SW(off));
                ldm_x4(aL[mt][0], aL[mt][1], aL[mt][2], aL[mt][3], stg + SW(off + 64));
            }
#pragma unroll
            for (int nt = 0; nt < 4; nt++) {
                uint32_t offB = b_base + nt * 1024 + kh * 32;
                uint32_t bh0, bh1, bl0, bl1;
                ldm_x2(bh0, bh1, stg + 16384 + SW(offB));
                ldm_x2(bl0, bl1, stg + 16384 + SW(offB + 64));
#pragma unroll
                for (int mt = 0; mt < 4; mt++) {
                    mma_bf16(acc[mt][nt], aH[mt], bh0, bh1);
                    mma_bf16(acc[mt][nt], aH[mt], bl0, bl1);
                    mma_bf16(acc[mt][nt], aL[mt], bh0, bh1);
                }
            }
        }
        if (c < 7) {
            stsA((c + 1) & 1);
            cp_wait0();
        }
        __syncthreads();
    }

    float* C = gm ? g_er : g_el;
    const float* bias = gm ? b_dst : b_src;
#pragma unroll
    for (int nt = 0; nt < 4; nt++) {
        int n = wn + nt * 8 + (lane & 3) * 2;
        float b0v = bias[n];
        float b1v = bias[n + 1];
#pragma unroll
        for (int mt = 0; mt < 4; mt++) {
            int m = m0 + wm + mt * 16 + (lane >> 2);
            if (m < NN) {
                float2 o = make_float2(acc[mt][nt][0] + b0v, acc[mt][nt][1] + b1v);
                *(float2*)(C + (size_t)m * HD + n) = o;
            }
            if (m + 8 < NN) {
                float2 o = make_float2(acc[mt][nt][2] + b0v, acc[mt][nt][3] + b1v);
                *(float2*)(C + (size_t)(m + 8) * HD + n) = o;
            }
        }
    }
}

// ---------------- CSR build ----------------
__global__ void zero_deg_kernel() {
    int i = blockIdx.x * blockDim.x + threadIdx.x;
    if (i < NN) g_deg[i] = 0;
}

__global__ void count_kernel(const int* __restrict__ dst) {
    int e4 = (blockIdx.x * blockDim.x + threadIdx.x) * 4;
    if (e4 < NE) {
        int4 d = *(const int4*)(dst + e4);
        atomicAdd(&g_deg[d.x], 1);
        atomicAdd(&g_deg[d.y], 1);
        atomicAdd(&g_deg[d.z], 1);
        atomicAdd(&g_deg[d.w], 1);
    }
}

__global__ void scan1_kernel() {   // 98 blocks x 1024
    __shared__ int sm[1024];
    int i = blockIdx.x * 1024 + threadIdx.x;
    int v = (i < NN) ? g_deg[i] : 0;
    sm[threadIdx.x] = v;
    __syncthreads();
    for (int off = 1; off < 1024; off <<= 1) {
        int t = (threadIdx.x >= off) ? sm[threadIdx.x - off] : 0;
        __syncthreads();
        sm[threadIdx.x] += t;
        __syncthreads();
    }
    if (i < NN) g_off[i] = sm[threadIdx.x] - v;   // exclusive
    if (threadIdx.x == 1023) g_bsum[blockIdx.x] = sm[1023];
}

__global__ void scan2_kernel() {   // 1 block x 128
    __shared__ int sm[128];
    int v = (threadIdx.x < 98) ? g_bsum[threadIdx.x] : 0;
    sm[threadIdx.x] = v;
    __syncthreads();
    for (int off = 1; off < 128; off <<= 1) {
        int t = (threadIdx.x >= off) ? sm[threadIdx.x - off] : 0;
        __syncthreads();
        sm[threadIdx.x] += t;
        __syncthreads();
    }
    if (threadIdx.x < 98) g_bsum[threadIdx.x] = sm[threadIdx.x] - v;
}

__global__ void scan3_kernel() {   // 98 blocks x 1024
    int i = blockIdx.x * 1024 + threadIdx.x;
    if (i < NN) {
        int o = g_off[i] + g_bsum[i >> 10];
        g_off[i] = o;
        g_cur[i] = o;
    }
    if (i == 0) g_off[NN] = NE;
}

__global__ void fill_kernel(const int* __restrict__ src, const int* __restrict__ dst) {
    int e4 = (blockIdx.x * blockDim.x + threadIdx.x) * 4;
    if (e4 < NE) {
        int4 d = *(const int4*)(dst + e4);
        int4 s = *(const int4*)(src + e4);
        int p;
        p = atomicAdd(&g_cur[d.x], 1); g_e[p] = make_int2(e4 + 0, s.x);
        p = atomicAdd(&g_cur[d.y], 1); g_e[p] = make_int2(e4 + 1, s.y);
        p = atomicAdd(&g_cur[d.z], 1); g_e[p] = make_int2(e4 + 2, s.z);
        p = atomicAdd(&g_cur[d.w], 1); g_e[p] = make_int2(e4 + 3, s.w);
    }
}

// ------- pull-based flash-softmax aggregation + fused edge output --------
__global__ void __launch_bounds__(256) node_kernel(const float* __restrict__ attn,
                                                   float* __restrict__ out) {
    int warp = (blockIdx.x * blockDim.x + threadIdx.x) >> 5;
    int lane = threadIdx.x & 31;
    if (warp >= NN) return;
    const int v = warp;

    const float4 rv = *(const float4*)&g_er[(size_t)v * HD + lane * 4];
    const float4 av = *(const float4*)&attn[lane * 4];

    const int beg = g_off[v];
    const int end = g_off[v + 1];

    float mval = -INFINITY;
    float lsum = 0.f;
    float4 acc = make_float4(0.f, 0.f, 0.f, 0.f);

    int2 cur = make_int2(0, 0), nxt = make_int2(0, 0);
    float4 lu = make_float4(0.f, 0.f, 0.f, 0.f);
    if (beg < end) {
        cur = g_e[beg];
        lu = *(const float4*)&g_el[(size_t)cur.y * HD + lane * 4];
        if (beg + 1 < end) nxt = g_e[beg + 1];
    }

    for (int ei = beg; ei < end; ei++) {
        float4 lu_n = make_float4(0.f, 0.f, 0.f, 0.f);
        int2 nxt2 = nxt;
        if (ei + 1 < end) {
            lu_n = *(const float4*)&g_el[(size_t)nxt.y * HD + lane * 4];
            if (ei + 2 < end) nxt2 = g_e[ei + 2];
        }

        float p = lrelu(lu.x + rv.x) * av.x;
        p = fmaf(lrelu(lu.y + rv.y), av.y, p);
        p = fmaf(lrelu(lu.z + rv.z), av.z, p);
        p = fmaf(lrelu(lu.w + rv.w), av.w, p);
        p += __shfl_xor_sync(0xffffffffu, p, 1);
        p += __shfl_xor_sync(0xffffffffu, p, 2);
        p += __shfl_xor_sync(0xffffffffu, p, 4);

        if ((lane & 7) == 0) g_s[(size_t)ei * 4 + (lane >> 3)] = p;

        float mnew  = fmaxf(mval, p);
        float scale = __expf(mval - mnew);
        float ww    = __expf(p - mnew);
        lsum = lsum * scale + ww;
        acc.x = fmaf(acc.x, scale, ww * lu.x);
        acc.y = fmaf(acc.y, scale, ww * lu.y);
        acc.z = fmaf(acc.z, scale, ww * lu.z);
        acc.w = fmaf(acc.w, scale, ww * lu.w);
        mval = mnew;

        cur = nxt;
        nxt = nxt2;
        lu = lu_n;
    }

    float inv = (lsum > 0.f) ? (1.0f / lsum) : 0.f;
    float4 r;
    r.x = acc.x * inv;
    r.y = acc.y * inv;
    r.z = acc.z * inv;
    r.w = acc.w * inv;
    r.x += __shfl_xor_sync(0xffffffffu, r.x, 8);
    r.y += __shfl_xor_sync(0xffffffffu, r.y, 8);
    r.z += __shfl_xor_sync(0xffffffffu, r.z, 8);
    r.w += __shfl_xor_sync(0xffffffffu, r.w, 8);
    r.x += __shfl_xor_sync(0xffffffffu, r.x, 16);
    r.y += __shfl_xor_sync(0xffffffffu, r.y, 16);
    r.z += __shfl_xor_sync(0xffffffffu, r.z, 16);
    r.w += __shfl_xor_sync(0xffffffffu, r.w, 16);

    if (lane < 8) {
        float4 o;
        o.x = r.x * 0.25f; o.y = r.y * 0.25f; o.z = r.z * 0.25f; o.w = r.w * 0.25f;
        *(float4*)&out[(size_t)v * 32 + lane * 4] = o;
    }

    __syncwarp();
    const float m0 = __shfl_sync(0xffffffffu, mval, 0);
    const float m1 = __shfl_sync(0xffffffffu, mval, 8);
    const float m2 = __shfl_sync(0xffffffffu, mval, 16);
    const float m3 = __shfl_sync(0xffffffffu, mval, 24);
    float l0 = __shfl_sync(0xffffffffu, lsum, 0);
    float l1 = __shfl_sync(0xffffffffu, lsum, 8);
    float l2 = __shfl_sync(0xffffffffu, lsum, 16);
    float l3 = __shfl_sync(0xffffffffu, lsum, 24);
    const float i0 = (l0 > 0.f) ? 0.25f / l0 : 0.f;
    const float i1 = (l1 > 0.f) ? 0.25f / l1 : 0.f;
    const float i2 = (l2 > 0.f) ? 0.25f / l2 : 0.f;
    const float i3 = (l3 > 0.f) ? 0.25f / l3 : 0.f;

    for (int idx = beg + lane; idx < end; idx += 32) {
        float4 s4 = *(const float4*)&g_s[(size_t)idx * 4];
        int eid = g_e[idx].x;
        float am = __expf(s4.x - m0) * i0;
        am = fmaf(__expf(s4.y - m1), i1, am);
        am = fmaf(__expf(s4.z - m2), i2, am);
        am = fmaf(__expf(s4.w - m3), i3, am);
        out[(size_t)NN * 32 + eid] = am;
    }
}

// ---------------- launch ----------------
extern "C" void kernel_launch(void* const* d_in, const int* in_sizes, int n_in,
                              void* d_out, int out_size) {
    const float* x     = (const float*)d_in[0];
    const float* w_src = (const float*)d_in[1];
    const float* b_src = (const float*)d_in[2];
    const float* w_dst = (const float*)d_in[3];
    const float* b_dst = (const float*)d_in[4];
    const float* attn  = (const float*)d_in[5];
    const int*   src   = (const int*)d_in[6];
    const int*   dst   = (const int*)d_in[7];
    float* out = (float*)d_out;

    cudaFuncSetAttribute(gemm2_kernel, cudaFuncAttributeMaxDynamicSharedMemorySize, SM_TOT);

    // Fork a second stream so the CSR build (src/dst only) runs concurrently
    // with the projection GEMM (x/w only). Host-side objects only; created and
    // destroyed within this call (which runs only for correctness + capture).
    cudaStream_t s2;
    cudaStreamCreateWithFlags(&s2, cudaStreamNonBlocking);
    cudaEvent_t evFork, evJoin;
    cudaEventCreateWithFlags(&evFork, cudaEventDisableTiming);
    cudaEventCreateWithFlags(&evJoin, cudaEventDisableTiming);

    cudaEventRecord(evFork, 0);
    cudaStreamWaitEvent(s2, evFork, 0);

    // stream 0: projection GEMM path
    wsplit_kernel<<<(2 * 8 * 128 * 32 + 255) / 256, 256>>>(w_src, w_dst);
    const int gemm_blocks = (NN + 127) / 128;     // 782
    gemm2_kernel<<<gemm_blocks, 512, SM_TOT>>>(x, b_src, b_dst);

    // stream s2: CSR build path
    zero_deg_kernel<<<(NN + 255) / 256, 256, 0, s2>>>();
    count_kernel<<<(NE / 4 + 255) / 256, 256, 0, s2>>>(dst);
    scan1_kernel<<<98, 1024, 0, s2>>>();
    scan2_kernel<<<1, 128, 0, s2>>>();
    scan3_kernel<<<98, 1024, 0, s2>>>();
    fill_kernel<<<(NE / 4 + 255) / 256, 256, 0, s2>>>(src, dst);

    cudaEventRecord(evJoin, s2);
    cudaStreamWaitEvent(0, evJoin, 0);

    node_kernel<<<(NN * 32 + 255) / 256, 256>>>(attn, out);

    cudaEventDestroy(evFork);
    cudaEventDestroy(evJoin);
    cudaStreamDestroy(s2);
}